// round 15
// baseline (speedup 1.0000x reference)
#include <cuda_runtime.h>
#include <cstdint>

typedef unsigned long long ull;

#define BHn 8
#define Nn  384
#define Dn  64
#define DP  72   // 64 d-channels + 1 den channel + 7 pad

// ---------------- device scratch (no allocations allowed) ----------------
__device__ float g_P[3][BHn][Nn][Dn];     // a, b, c
__device__ float g_V1[BHn][Nn][DP];       // v1 padded (col 64 = 1, 65..71 = 0)
__device__ float g_V2[BHn][Nn][DP];       // v2 padded
__device__ float g_E[3][BHn][Nn][Nn];     // eAB, eCD, eEF
__device__ float g_NUM[2][BHn][Nn][DP];   // partial sums per j-half

// ---------------- packed f32x2 helpers ----------------
__device__ __forceinline__ ull pack2(float x) {
    ull r; asm("mov.b64 %0, {%1, %1};" : "=l"(r) : "f"(x)); return r;
}
__device__ __forceinline__ void fma2(ull& d, ull a, ull b) {
    asm("fma.rn.f32x2 %0, %1, %2, %0;" : "+l"(d) : "l"(a), "l"(b));
}
__device__ __forceinline__ ull mul2(ull a, ull b) {
    ull r; asm("mul.rn.f32x2 %0, %1, %2;" : "=l"(r) : "l"(a), "l"(b)); return r;
}
__device__ __forceinline__ ull add2(ull a, ull b) {
    ull r; asm("add.rn.f32x2 %0, %1, %2;" : "=l"(r) : "l"(a), "l"(b)); return r;
}
__device__ __forceinline__ float2 unpack2(ull v) {
    float2 f; asm("mov.b64 {%0, %1}, %2;" : "=f"(f.x), "=f"(f.y) : "l"(v)); return f;
}

// ---------------- stage 0: init pad channels ----------------
__global__ void init_kernel() {
    int idx = blockIdx.x * 256 + threadIdx.x;   // BHn*Nn*8 = 24576
    if (idx >= BHn * Nn * 8) return;
    int c  = idx & 7;
    int n  = (idx >> 3) % Nn;
    int bh = idx / (Nn * 8);
    float v = (c == 0) ? 1.f : 0.f;   // channel 64 (den) = 1, 65..71 = 0
    g_V1[bh][n][64 + c] = v;
    g_V2[bh][n][64 + c] = v;
}

// ---------------- stage 1: projection GEMM ----------------
// out[m=b*384+n, g in 0..1279] = sum_c x[m,c] * W[wrow(g), c]
// g -> s5 = g/256 (maps to original slice {0,1,2,6,7}), h = (g/64)%4, d = g%64
__global__ __launch_bounds__(256) void proj_kernel(const float* __restrict__ x,
                                                   const float* __restrict__ W) {
    __shared__ float sX[16][68];
    __shared__ float sW[16][68];
    int t  = threadIdx.x;
    int tx = t & 15, ty = t >> 4;
    int m0 = blockIdx.y * 64;
    int n0 = blockIdx.x * 64;

    int lm = t >> 2;          // 0..63
    int lk = (t & 3) * 4;     // 0,4,8,12

    int g0 = n0 + lm;
    int s5 = g0 >> 8;
    int orig_s = s5 + (s5 >= 3 ? 3 : 0);    // {0,1,2,6,7}
    int wrow = orig_s * 256 + (g0 & 255);

    float acc[4][4];
#pragma unroll
    for (int r = 0; r < 4; r++)
#pragma unroll
        for (int s = 0; s < 4; s++) acc[r][s] = 0.f;

    for (int k0 = 0; k0 < 256; k0 += 16) {
        float4 xv = *(const float4*)&x[(m0 + lm) * 256 + k0 + lk];
        float4 wv = *(const float4*)&W[wrow * 256 + k0 + lk];
        sX[lk + 0][lm] = xv.x; sX[lk + 1][lm] = xv.y; sX[lk + 2][lm] = xv.z; sX[lk + 3][lm] = xv.w;
        sW[lk + 0][lm] = wv.x; sW[lk + 1][lm] = wv.y; sW[lk + 2][lm] = wv.z; sW[lk + 3][lm] = wv.w;
        __syncthreads();
#pragma unroll
        for (int kk = 0; kk < 16; kk++) {
            float4 a4 = *(const float4*)&sX[kk][ty * 4];
            float4 b4 = *(const float4*)&sW[kk][tx * 4];
            float a[4] = {a4.x, a4.y, a4.z, a4.w};
            float b[4] = {b4.x, b4.y, b4.z, b4.w};
#pragma unroll
            for (int r = 0; r < 4; r++)
#pragma unroll
                for (int s = 0; s < 4; s++) acc[r][s] += a[r] * b[s];
        }
        __syncthreads();
    }

#pragma unroll
    for (int r = 0; r < 4; r++) {
        int m = m0 + ty * 4 + r;
        int b = m / Nn, n = m % Nn;
#pragma unroll
        for (int s = 0; s < 4; s++) {
            int gg = n0 + tx * 4 + s;
            int ss = gg >> 8;
            int h = (gg >> 6) & 3;
            int d = gg & 63;
            int bh = b * 4 + h;
            float v = acc[r][s];
            if (ss < 3)       g_P[ss][bh][n][d] = v;
            else if (ss == 3) g_V1[bh][n][d] = v;
            else              g_V2[bh][n][d] = v;
        }
    }
}

// ---------------- stage 2: pairwise exp logits ----------------
// p=0: eAB = exp(a.b^T/8); p=1: eCD = exp(b.c^T/8); p=2: eEF = exp(c.a^T/8)
__global__ __launch_bounds__(256) void logits_kernel() {
    int p  = blockIdx.z >> 3;
    int bh = blockIdx.z & 7;
    int i0 = blockIdx.y * 64, j0 = blockIdx.x * 64;
    const float* X = &g_P[p][bh][0][0];
    const float* Y = &g_P[(p + 1) % 3][bh][0][0];
    float* E = &g_E[p][bh][0][0];

    __shared__ float sX[64][68];
    __shared__ float sY[64][68];
    int t = threadIdx.x, tx = t & 15, ty = t >> 4;

    int lm  = t >> 2;           // 0..63
    int lk0 = (t & 3) * 16;     // 0,16,32,48
#pragma unroll
    for (int u = 0; u < 16; u += 4) {
        float4 xv = *(const float4*)&X[(i0 + lm) * 64 + lk0 + u];
        sX[lk0 + u + 0][lm] = xv.x; sX[lk0 + u + 1][lm] = xv.y;
        sX[lk0 + u + 2][lm] = xv.z; sX[lk0 + u + 3][lm] = xv.w;
        float4 yv = *(const float4*)&Y[(j0 + lm) * 64 + lk0 + u];
        sY[lk0 + u + 0][lm] = yv.x; sY[lk0 + u + 1][lm] = yv.y;
        sY[lk0 + u + 2][lm] = yv.z; sY[lk0 + u + 3][lm] = yv.w;
    }
    __syncthreads();

    float acc[4][4];
#pragma unroll
    for (int r = 0; r < 4; r++)
#pragma unroll
        for (int s = 0; s < 4; s++) acc[r][s] = 0.f;

#pragma unroll
    for (int kk = 0; kk < 64; kk++) {
        float4 a4 = *(const float4*)&sX[kk][ty * 4];
        float4 b4 = *(const float4*)&sY[kk][tx * 4];
        float a[4] = {a4.x, a4.y, a4.z, a4.w};
        float b[4] = {b4.x, b4.y, b4.z, b4.w};
#pragma unroll
        for (int r = 0; r < 4; r++)
#pragma unroll
            for (int s = 0; s < 4; s++) acc[r][s] += a[r] * b[s];
    }

#pragma unroll
    for (int r = 0; r < 4; r++)
#pragma unroll
        for (int s = 0; s < 4; s++)
            E[(i0 + ty * 4 + r) * Nn + (j0 + tx * 4 + s)] = __expf(acc[r][s] * 0.125f);
}

// ---------------- stage 3: main N^3*(D+1) contraction ----------------
// block: (chunk 0..8, i-tile 0..5, bh*2+jhalf)
// num[i, dbase+c] += sum_{j in half} eAB[i,j]*v1[j,dbase+c] * (sum_k eCD[i,k]*eEF[j,k]*v2[k,dbase+c])
__global__ __launch_bounds__(256, 2) void main_kernel() {
    int chunk = blockIdx.x;         // 0..8
    int it    = blockIdx.y;         // 0..5
    int bh    = blockIdx.z >> 1;    // 0..7
    int jh    = blockIdx.z & 1;     // 0..1
    int i0    = it * 64;
    int dbase = chunk * 8;

    const float* __restrict__ eAB = &g_E[0][bh][0][0];
    const float* __restrict__ eCD = &g_E[1][bh][0][0];
    const float* __restrict__ eEF = &g_E[2][bh][0][0];
    const float* __restrict__ V1  = &g_V1[bh][0][0];
    const float* __restrict__ V2  = &g_V2[bh][0][0];

    __shared__ float sCDt[32][64];   // [kk][ii]  A-tile (eCD), transposed
    __shared__ float sB[32][128];    // [kk][j*8+c] = eEF[j0+j][k]*v2[k][dbase+c]

    int t = threadIdx.x;
    int tx = t & 15, ty = t >> 4;    // thread's j = j0+tx ; rows i0+ty*4..+3

    ull numacc[4][4];
#pragma unroll
    for (int r = 0; r < 4; r++)
#pragma unroll
        for (int q = 0; q < 4; q++) numacc[r][q] = 0ULL;

    // per-thread load coordinates
    int a_ii = t >> 2;             // 0..63
    int a_kk = (t & 3) * 8;        // 0,8,16,24
    int b_kk = t >> 3;             // 0..31
    int b_nn = (t & 7) * 16;       // 0..112
    int b_jj = b_nn >> 3;          // local j (even)

    int jend = jh * 192 + 192;
    for (int j0 = jh * 192; j0 < jend; j0 += 16) {
        ull R[4][4];
#pragma unroll
        for (int r = 0; r < 4; r++)
#pragma unroll
            for (int q = 0; q < 4; q++) R[r][q] = 0ULL;

        for (int k0 = 0; k0 < 384; k0 += 32) {
            // load eCD tile transposed
            {
                const float* src = &eCD[(i0 + a_ii) * Nn + k0 + a_kk];
                float4 v0 = *(const float4*)src;
                float4 v1_ = *(const float4*)(src + 4);
                sCDt[a_kk + 0][a_ii] = v0.x;  sCDt[a_kk + 1][a_ii] = v0.y;
                sCDt[a_kk + 2][a_ii] = v0.z;  sCDt[a_kk + 3][a_ii] = v0.w;
                sCDt[a_kk + 4][a_ii] = v1_.x; sCDt[a_kk + 5][a_ii] = v1_.y;
                sCDt[a_kk + 6][a_ii] = v1_.z; sCDt[a_kk + 7][a_ii] = v1_.w;
            }
            // build B tile: sB[kk][j*8+c] = eEF[j0+j][k0+kk] * V2[k0+kk][dbase+c]
            {
                float ef0 = eEF[(j0 + b_jj) * Nn + k0 + b_kk];
                float ef1 = eEF[(j0 + b_jj + 1) * Nn + k0 + b_kk];
                const float* v2r = &V2[(k0 + b_kk) * DP + dbase];
                float4 va = *(const float4*)v2r;
                float4 vb = *(const float4*)(v2r + 4);
                float* d0 = &sB[b_kk][b_nn];
                ((float4*)d0)[0] = make_float4(ef0 * va.x, ef0 * va.y, ef0 * va.z, ef0 * va.w);
                ((float4*)d0)[1] = make_float4(ef0 * vb.x, ef0 * vb.y, ef0 * vb.z, ef0 * vb.w);
                ((float4*)d0)[2] = make_float4(ef1 * va.x, ef1 * va.y, ef1 * va.z, ef1 * va.w);
                ((float4*)d0)[3] = make_float4(ef1 * vb.x, ef1 * vb.y, ef1 * vb.z, ef1 * vb.w);
            }
            __syncthreads();
#pragma unroll
            for (int kk = 0; kk < 32; kk++) {
                float4 av = *(const float4*)&sCDt[kk][ty * 4];
                ulonglong2 b01 = *(const ulonglong2*)&sB[kk][tx * 8];
                ulonglong2 b23 = *(const ulonglong2*)&sB[kk][tx * 8 + 4];
                ull a0 = pack2(av.x), a1 = pack2(av.y), a2 = pack2(av.z), a3 = pack2(av.w);
                fma2(R[0][0], a0, b01.x); fma2(R[0][1], a0, b01.y);
                fma2(R[0][2], a0, b23.x); fma2(R[0][3], a0, b23.y);
                fma2(R[1][0], a1, b01.x); fma2(R[1][1], a1, b01.y);
                fma2(R[1][2], a1, b23.x); fma2(R[1][3], a1, b23.y);
                fma2(R[2][0], a2, b01.x); fma2(R[2][1], a2, b01.y);
                fma2(R[2][2], a2, b23.x); fma2(R[2][3], a2, b23.y);
                fma2(R[3][0], a3, b01.x); fma2(R[3][1], a3, b01.y);
                fma2(R[3][2], a3, b23.x); fma2(R[3][3], a3, b23.y);
            }
            __syncthreads();
        }

        // epilogue for this j-tile: num += eAB[i,j]*v1[j,c]*R
        const float* v1r = &V1[(j0 + tx) * DP + dbase];
        ulonglong2 u01 = *(const ulonglong2*)v1r;
        ulonglong2 u23 = *(const ulonglong2*)(v1r + 4);
#pragma unroll
        for (int r = 0; r < 4; r++) {
            float w = eAB[(i0 + ty * 4 + r) * Nn + (j0 + tx)];
            ull w2 = pack2(w);
            fma2(numacc[r][0], w2, mul2(u01.x, R[r][0]));
            fma2(numacc[r][1], w2, mul2(u01.y, R[r][1]));
            fma2(numacc[r][2], w2, mul2(u23.x, R[r][2]));
            fma2(numacc[r][3], w2, mul2(u23.y, R[r][3]));
        }
    }

    // deterministic reduction across tx (16 lanes within half-warp), then write
#pragma unroll
    for (int r = 0; r < 4; r++)
#pragma unroll
        for (int q = 0; q < 4; q++) {
            ull v = numacc[r][q];
#pragma unroll
            for (int off = 8; off > 0; off >>= 1)
                v = add2(v, __shfl_xor_sync(0xffffffffu, v, off));
            numacc[r][q] = v;
        }
    if (tx == 0) {
#pragma unroll
        for (int r = 0; r < 4; r++) {
            float* dst = &g_NUM[jh][bh][i0 + ty * 4 + r][dbase];
#pragma unroll
            for (int q = 0; q < 4; q++) {
                float2 f = unpack2(numacc[r][q]);
                dst[q * 2 + 0] = f.x;
                dst[q * 2 + 1] = f.y;
            }
        }
    }
}

// ---------------- stage 4: divide + layout ----------------
__global__ void final_kernel(float* __restrict__ out) {
    int idx = blockIdx.x * 256 + threadIdx.x;   // 2*384*256 = 196608
    if (idx >= 2 * Nn * 256) return;
    int c = idx & 255;
    int n = (idx >> 8) % Nn;
    int b = idx / (Nn * 256);
    int h = c >> 6, d = c & 63;
    int bh = b * 4 + h;
    float num = g_NUM[0][bh][n][d]  + g_NUM[1][bh][n][d];
    float den = g_NUM[0][bh][n][64] + g_NUM[1][bh][n][64];
    out[idx] = num / den;
}

// ---------------- launch ----------------
extern "C" void kernel_launch(void* const* d_in, const int* in_sizes, int n_in,
                              void* d_out, int out_size) {
    const float* x = (const float*)d_in[0];
    const float* W = (const float*)d_in[1];
    // defensive: x has 196608 elems, W has 524288
    if (n_in >= 2 && in_sizes[0] == 8 * 256 * 256) { const float* tmp = x; x = W; W = tmp; }
    float* out = (float*)d_out;

    init_kernel<<<96, 256>>>();
    proj_kernel<<<dim3(20, 12), 256>>>(x, W);
    logits_kernel<<<dim3(6, 6, 24), 256>>>();
    main_kernel<<<dim3(9, 6, 16), 256>>>();
    final_kernel<<<768, 256>>>(out);
    (void)out_size;
}

// round 16
// speedup vs baseline: 1.0003x; 1.0003x over previous
#include <cuda_runtime.h>
#include <cstdint>

typedef unsigned long long ull;

#define BHn 8
#define Nn  384
#define Dn  64
#define DP  72   // 64 d-channels + 1 den channel + 7 pad

// ---------------- device scratch (no allocations allowed) ----------------
__device__ float g_P[3][BHn][Nn][Dn];     // a, b, c
__device__ float g_V1[BHn][Nn][DP];       // v1 padded (col 64 = 1, 65..71 = 0)
__device__ float g_V2[BHn][Nn][DP];       // v2 padded
__device__ float g_E[3][BHn][Nn][Nn];     // eAB, eCD, eEF
__device__ float g_NUM[2][BHn][Nn][DP];   // partial sums per j-half

// ---------------- packed f32x2 helpers ----------------
__device__ __forceinline__ ull pack2(float x) {
    ull r; asm("mov.b64 %0, {%1, %1};" : "=l"(r) : "f"(x)); return r;
}
__device__ __forceinline__ void fma2(ull& d, ull a, ull b) {
    asm("fma.rn.f32x2 %0, %1, %2, %0;" : "+l"(d) : "l"(a), "l"(b));
}
__device__ __forceinline__ ull mul2(ull a, ull b) {
    ull r; asm("mul.rn.f32x2 %0, %1, %2;" : "=l"(r) : "l"(a), "l"(b)); return r;
}
__device__ __forceinline__ ull add2(ull a, ull b) {
    ull r; asm("add.rn.f32x2 %0, %1, %2;" : "=l"(r) : "l"(a), "l"(b)); return r;
}
__device__ __forceinline__ float2 unpack2(ull v) {
    float2 f; asm("mov.b64 {%0, %1}, %2;" : "=f"(f.x), "=f"(f.y) : "l"(v)); return f;
}

// ---------------- stage 0: init pad channels ----------------
__global__ void init_kernel() {
    int idx = blockIdx.x * 256 + threadIdx.x;   // BHn*Nn*8 = 24576
    if (idx >= BHn * Nn * 8) return;
    int c  = idx & 7;
    int n  = (idx >> 3) % Nn;
    int bh = idx / (Nn * 8);
    float v = (c == 0) ? 1.f : 0.f;   // channel 64 (den) = 1, 65..71 = 0
    g_V1[bh][n][64 + c] = v;
    g_V2[bh][n][64 + c] = v;
}

// ---------------- stage 1: projection GEMM ----------------
// out[m=b*384+n, g in 0..1279] = sum_c x[m,c] * W[wrow(g), c]
// g -> s5 = g/256 (maps to original slice {0,1,2,6,7}), h = (g/64)%4, d = g%64
__global__ __launch_bounds__(256) void proj_kernel(const float* __restrict__ x,
                                                   const float* __restrict__ W) {
    __shared__ float sX[16][68];
    __shared__ float sW[16][68];
    int t  = threadIdx.x;
    int tx = t & 15, ty = t >> 4;
    int m0 = blockIdx.y * 64;
    int n0 = blockIdx.x * 64;

    int lm = t >> 2;          // 0..63
    int lk = (t & 3) * 4;     // 0,4,8,12

    int g0 = n0 + lm;
    int s5 = g0 >> 8;
    int orig_s = s5 + (s5 >= 3 ? 3 : 0);    // {0,1,2,6,7}
    int wrow = orig_s * 256 + (g0 & 255);

    float acc[4][4];
#pragma unroll
    for (int r = 0; r < 4; r++)
#pragma unroll
        for (int s = 0; s < 4; s++) acc[r][s] = 0.f;

    for (int k0 = 0; k0 < 256; k0 += 16) {
        float4 xv = *(const float4*)&x[(m0 + lm) * 256 + k0 + lk];
        float4 wv = *(const float4*)&W[wrow * 256 + k0 + lk];
        sX[lk + 0][lm] = xv.x; sX[lk + 1][lm] = xv.y; sX[lk + 2][lm] = xv.z; sX[lk + 3][lm] = xv.w;
        sW[lk + 0][lm] = wv.x; sW[lk + 1][lm] = wv.y; sW[lk + 2][lm] = wv.z; sW[lk + 3][lm] = wv.w;
        __syncthreads();
#pragma unroll
        for (int kk = 0; kk < 16; kk++) {
            float4 a4 = *(const float4*)&sX[kk][ty * 4];
            float4 b4 = *(const float4*)&sW[kk][tx * 4];
            float a[4] = {a4.x, a4.y, a4.z, a4.w};
            float b[4] = {b4.x, b4.y, b4.z, b4.w};
#pragma unroll
            for (int r = 0; r < 4; r++)
#pragma unroll
                for (int s = 0; s < 4; s++) acc[r][s] += a[r] * b[s];
        }
        __syncthreads();
    }

#pragma unroll
    for (int r = 0; r < 4; r++) {
        int m = m0 + ty * 4 + r;
        int b = m / Nn, n = m % Nn;
#pragma unroll
        for (int s = 0; s < 4; s++) {
            int gg = n0 + tx * 4 + s;
            int ss = gg >> 8;
            int h = (gg >> 6) & 3;
            int d = gg & 63;
            int bh = b * 4 + h;
            float v = acc[r][s];
            if (ss < 3)       g_P[ss][bh][n][d] = v;
            else if (ss == 3) g_V1[bh][n][d] = v;
            else              g_V2[bh][n][d] = v;
        }
    }
}

// ---------------- stage 2: pairwise exp logits ----------------
// p=0: eAB = exp(a.b^T/8); p=1: eCD = exp(b.c^T/8); p=2: eEF = exp(c.a^T/8)
__global__ __launch_bounds__(256) void logits_kernel() {
    int p  = blockIdx.z >> 3;
    int bh = blockIdx.z & 7;
    int i0 = blockIdx.y * 64, j0 = blockIdx.x * 64;
    const float* X = &g_P[p][bh][0][0];
    const float* Y = &g_P[(p + 1) % 3][bh][0][0];
    float* E = &g_E[p][bh][0][0];

    __shared__ float sX[64][68];
    __shared__ float sY[64][68];
    int t = threadIdx.x, tx = t & 15, ty = t >> 4;

    int lm  = t >> 2;           // 0..63
    int lk0 = (t & 3) * 16;     // 0,16,32,48
#pragma unroll
    for (int u = 0; u < 16; u += 4) {
        float4 xv = *(const float4*)&X[(i0 + lm) * 64 + lk0 + u];
        sX[lk0 + u + 0][lm] = xv.x; sX[lk0 + u + 1][lm] = xv.y;
        sX[lk0 + u + 2][lm] = xv.z; sX[lk0 + u + 3][lm] = xv.w;
        float4 yv = *(const float4*)&Y[(j0 + lm) * 64 + lk0 + u];
        sY[lk0 + u + 0][lm] = yv.x; sY[lk0 + u + 1][lm] = yv.y;
        sY[lk0 + u + 2][lm] = yv.z; sY[lk0 + u + 3][lm] = yv.w;
    }
    __syncthreads();

    float acc[4][4];
#pragma unroll
    for (int r = 0; r < 4; r++)
#pragma unroll
        for (int s = 0; s < 4; s++) acc[r][s] = 0.f;

#pragma unroll
    for (int kk = 0; kk < 64; kk++) {
        float4 a4 = *(const float4*)&sX[kk][ty * 4];
        float4 b4 = *(const float4*)&sY[kk][tx * 4];
        float a[4] = {a4.x, a4.y, a4.z, a4.w};
        float b[4] = {b4.x, b4.y, b4.z, b4.w};
#pragma unroll
        for (int r = 0; r < 4; r++)
#pragma unroll
            for (int s = 0; s < 4; s++) acc[r][s] += a[r] * b[s];
    }

#pragma unroll
    for (int r = 0; r < 4; r++)
#pragma unroll
        for (int s = 0; s < 4; s++)
            E[(i0 + ty * 4 + r) * Nn + (j0 + tx * 4 + s)] = __expf(acc[r][s] * 0.125f);
}

// ---------------- stage 3: main N^3*(D+1) contraction ----------------
// block: (chunk 0..8, i-tile 0..5, bh*2+jhalf)
// num[i, dbase+c] += sum_{j in half} eAB[i,j]*v1[j,dbase+c] * (sum_k eCD[i,k]*eEF[j,k]*v2[k,dbase+c])
__global__ __launch_bounds__(256, 2) void main_kernel() {
    int chunk = blockIdx.x;         // 0..8
    int it    = blockIdx.y;         // 0..5
    int bh    = blockIdx.z >> 1;    // 0..7
    int jh    = blockIdx.z & 1;     // 0..1
    int i0    = it * 64;
    int dbase = chunk * 8;

    const float* __restrict__ eAB = &g_E[0][bh][0][0];
    const float* __restrict__ eCD = &g_E[1][bh][0][0];
    const float* __restrict__ eEF = &g_E[2][bh][0][0];
    const float* __restrict__ V1  = &g_V1[bh][0][0];
    const float* __restrict__ V2  = &g_V2[bh][0][0];

    __shared__ float sCDt[32][64];   // [kk][ii]  A-tile (eCD), transposed
    __shared__ float sB[32][128];    // [kk][j*8+c] = eEF[j0+j][k]*v2[k][dbase+c]

    int t = threadIdx.x;
    int tx = t & 15, ty = t >> 4;    // thread's j = j0+tx ; rows i0+ty*4..+3

    ull numacc[4][4];
#pragma unroll
    for (int r = 0; r < 4; r++)
#pragma unroll
        for (int q = 0; q < 4; q++) numacc[r][q] = 0ULL;

    // per-thread load coordinates
    int a_ii = t >> 2;             // 0..63
    int a_kk = (t & 3) * 8;        // 0,8,16,24
    int b_kk = t >> 3;             // 0..31
    int b_nn = (t & 7) * 16;       // 0..112
    int b_jj = b_nn >> 3;          // local j (even)

    int jend = jh * 192 + 192;
    for (int j0 = jh * 192; j0 < jend; j0 += 16) {
        ull R[4][4];
#pragma unroll
        for (int r = 0; r < 4; r++)
#pragma unroll
            for (int q = 0; q < 4; q++) R[r][q] = 0ULL;

        for (int k0 = 0; k0 < 384; k0 += 32) {
            // load eCD tile transposed
            {
                const float* src = &eCD[(i0 + a_ii) * Nn + k0 + a_kk];
                float4 v0 = *(const float4*)src;
                float4 v1_ = *(const float4*)(src + 4);
                sCDt[a_kk + 0][a_ii] = v0.x;  sCDt[a_kk + 1][a_ii] = v0.y;
                sCDt[a_kk + 2][a_ii] = v0.z;  sCDt[a_kk + 3][a_ii] = v0.w;
                sCDt[a_kk + 4][a_ii] = v1_.x; sCDt[a_kk + 5][a_ii] = v1_.y;
                sCDt[a_kk + 6][a_ii] = v1_.z; sCDt[a_kk + 7][a_ii] = v1_.w;
            }
            // build B tile: sB[kk][j*8+c] = eEF[j0+j][k0+kk] * V2[k0+kk][dbase+c]
            {
                float ef0 = eEF[(j0 + b_jj) * Nn + k0 + b_kk];
                float ef1 = eEF[(j0 + b_jj + 1) * Nn + k0 + b_kk];
                const float* v2r = &V2[(k0 + b_kk) * DP + dbase];
                float4 va = *(const float4*)v2r;
                float4 vb = *(const float4*)(v2r + 4);
                float* d0 = &sB[b_kk][b_nn];
                ((float4*)d0)[0] = make_float4(ef0 * va.x, ef0 * va.y, ef0 * va.z, ef0 * va.w);
                ((float4*)d0)[1] = make_float4(ef0 * vb.x, ef0 * vb.y, ef0 * vb.z, ef0 * vb.w);
                ((float4*)d0)[2] = make_float4(ef1 * va.x, ef1 * va.y, ef1 * va.z, ef1 * va.w);
                ((float4*)d0)[3] = make_float4(ef1 * vb.x, ef1 * vb.y, ef1 * vb.z, ef1 * vb.w);
            }
            __syncthreads();
#pragma unroll
            for (int kk = 0; kk < 32; kk++) {
                float4 av = *(const float4*)&sCDt[kk][ty * 4];
                ulonglong2 b01 = *(const ulonglong2*)&sB[kk][tx * 8];
                ulonglong2 b23 = *(const ulonglong2*)&sB[kk][tx * 8 + 4];
                ull a0 = pack2(av.x), a1 = pack2(av.y), a2 = pack2(av.z), a3 = pack2(av.w);
                fma2(R[0][0], a0, b01.x); fma2(R[0][1], a0, b01.y);
                fma2(R[0][2], a0, b23.x); fma2(R[0][3], a0, b23.y);
                fma2(R[1][0], a1, b01.x); fma2(R[1][1], a1, b01.y);
                fma2(R[1][2], a1, b23.x); fma2(R[1][3], a1, b23.y);
                fma2(R[2][0], a2, b01.x); fma2(R[2][1], a2, b01.y);
                fma2(R[2][2], a2, b23.x); fma2(R[2][3], a2, b23.y);
                fma2(R[3][0], a3, b01.x); fma2(R[3][1], a3, b01.y);
                fma2(R[3][2], a3, b23.x); fma2(R[3][3], a3, b23.y);
            }
            __syncthreads();
        }

        // epilogue for this j-tile: num += eAB[i,j]*v1[j,c]*R
        const float* v1r = &V1[(j0 + tx) * DP + dbase];
        ulonglong2 u01 = *(const ulonglong2*)v1r;
        ulonglong2 u23 = *(const ulonglong2*)(v1r + 4);
#pragma unroll
        for (int r = 0; r < 4; r++) {
            float w = eAB[(i0 + ty * 4 + r) * Nn + (j0 + tx)];
            ull w2 = pack2(w);
            fma2(numacc[r][0], w2, mul2(u01.x, R[r][0]));
            fma2(numacc[r][1], w2, mul2(u01.y, R[r][1]));
            fma2(numacc[r][2], w2, mul2(u23.x, R[r][2]));
            fma2(numacc[r][3], w2, mul2(u23.y, R[r][3]));
        }
    }

    // deterministic reduction across tx (16 lanes within half-warp), then write
#pragma unroll
    for (int r = 0; r < 4; r++)
#pragma unroll
        for (int q = 0; q < 4; q++) {
            ull v = numacc[r][q];
#pragma unroll
            for (int off = 8; off > 0; off >>= 1)
                v = add2(v, __shfl_xor_sync(0xffffffffu, v, off));
            numacc[r][q] = v;
        }
    if (tx == 0) {
#pragma unroll
        for (int r = 0; r < 4; r++) {
            float* dst = &g_NUM[jh][bh][i0 + ty * 4 + r][dbase];
#pragma unroll
            for (int q = 0; q < 4; q++) {
                float2 f = unpack2(numacc[r][q]);
                dst[q * 2 + 0] = f.x;
                dst[q * 2 + 1] = f.y;
            }
        }
    }
}

// ---------------- stage 4: divide + layout ----------------
__global__ void final_kernel(float* __restrict__ out) {
    int idx = blockIdx.x * 256 + threadIdx.x;   // 2*384*256 = 196608
    if (idx >= 2 * Nn * 256) return;
    int c = idx & 255;
    int n = (idx >> 8) % Nn;
    int b = idx / (Nn * 256);
    int h = c >> 6, d = c & 63;
    int bh = b * 4 + h;
    float num = g_NUM[0][bh][n][d]  + g_NUM[1][bh][n][d];
    float den = g_NUM[0][bh][n][64] + g_NUM[1][bh][n][64];
    out[idx] = num / den;
}

// ---------------- launch ----------------
extern "C" void kernel_launch(void* const* d_in, const int* in_sizes, int n_in,
                              void* d_out, int out_size) {
    const float* x = (const float*)d_in[0];
    const float* W = (const float*)d_in[1];
    // defensive: x has 196608 elems, W has 524288
    if (n_in >= 2 && in_sizes[0] == 8 * 256 * 256) { const float* tmp = x; x = W; W = tmp; }
    float* out = (float*)d_out;

    init_kernel<<<96, 256>>>();
    proj_kernel<<<dim3(20, 12), 256>>>(x, W);
    logits_kernel<<<dim3(6, 6, 24), 256>>>();
    main_kernel<<<dim3(9, 6, 16), 256>>>();
    final_kernel<<<768, 256>>>(out);
    (void)out_size;
}